// round 5
// baseline (speedup 1.0000x reference)
#include <cuda_runtime.h>
#include <math.h>

#define N_NODES 8192
#define F_IN 128
#define F_OUT 64
#define NEG_SLOPE 0.2f
#define VERY_SMALL 1000000000000.0f
#define SD_BLOCKS 64
#define ROWS_PER_SD_BLOCK (N_NODES / SD_BLOCKS)   // 128

__device__ float g_s[N_NODES];
__device__ float g_d[N_NODES];
__device__ float g_bmax[SD_BLOCKS];   // per-block max of d

// Kernel A: fused prep + sd + per-block d-max.
__global__ __launch_bounds__(256) void sd_kernel(const float* __restrict__ h,
                                                 const float* __restrict__ w,
                                                 const float* __restrict__ a) {
    __shared__ float sw[F_IN * 65];   // padded: conflict-free row reads
    __shared__ float sa[F_IN];
    __shared__ float ws[F_IN];
    __shared__ float wd[F_IN];
    __shared__ float wmax[8];
    const int t = threadIdx.x;

    if (t < F_IN) sa[t] = a[t];
    const float4* w4 = reinterpret_cast<const float4*>(w);
    #pragma unroll
    for (int r = 0; r < 8; ++r) {
        int f = t + r * 256;
        float4 v = w4[f];
        int k = f >> 4;
        int j = (f & 15) * 4;
        float* dst = &sw[k * 65 + j];
        dst[0] = v.x; dst[1] = v.y; dst[2] = v.z; dst[3] = v.w;
    }
    __syncthreads();

    {   // threads 0-127: ws[k]; 128-255: wd[k]
        int k = t & 127;
        const float* arow = sa + ((t >= 128) ? F_OUT : 0);
        const float* wrow = &sw[k * 65];
        float acc = 0.f;
        #pragma unroll
        for (int j = 0; j < F_OUT; ++j)
            acc += wrow[j] * arow[j];
        if (t < 128) ws[k] = acc; else wd[k] = acc;
    }
    __syncthreads();

    const int warp = t >> 5;
    const int lane = t & 31;
    const int base = blockIdx.x * ROWS_PER_SD_BLOCK + warp * (ROWS_PER_SD_BLOCK / 8);
    const float4 wsv = reinterpret_cast<const float4*>(ws)[lane];
    const float4 wdv = reinterpret_cast<const float4*>(wd)[lane];

    float dmax = -INFINITY;
    #pragma unroll
    for (int rr = 0; rr < ROWS_PER_SD_BLOCK / 8; ++rr) {
        const int i = base + rr;
        float4 hv = reinterpret_cast<const float4*>(h + (size_t)i * F_IN)[lane];
        float s = hv.x * wsv.x + hv.y * wsv.y + hv.z * wsv.z + hv.w * wsv.w;
        float d = hv.x * wdv.x + hv.y * wdv.y + hv.z * wdv.z + hv.w * wdv.w;
        #pragma unroll
        for (int o = 16; o > 0; o >>= 1) {
            s += __shfl_xor_sync(0xffffffffu, s, o);
            d += __shfl_xor_sync(0xffffffffu, d, o);
        }
        if (lane == 0) { g_s[i] = s; g_d[i] = d; dmax = fmaxf(dmax, d); }
    }
    if (lane == 0) wmax[warp] = dmax;
    __syncthreads();
    if (t == 0) {
        float m = wmax[0];
        #pragma unroll
        for (int k = 1; k < 8; ++k) m = fmaxf(m, wmax[k]);
        g_bmax[blockIdx.x] = m;
    }
}

__device__ __forceinline__ float block_reduce_sum(float v, float* red) {
    #pragma unroll
    for (int o = 16; o > 0; o >>= 1)
        v += __shfl_xor_sync(0xffffffffu, v, o);
    int warp = threadIdx.x >> 5;
    if ((threadIdx.x & 31) == 0) red[warp] = v;
    __syncthreads();
    if (warp == 0) {
        float x = (threadIdx.x < 8) ? red[threadIdx.x] : 0.f;
        #pragma unroll
        for (int o = 4; o > 0; o >>= 1)
            x += __shfl_xor_sync(0xffffffffu, x, o);
        if (threadIdx.x == 0) red[0] = x;
    }
    __syncthreads();
    return red[0];
}

// Kernel B: one CTA (256 threads) per row. Exp values stashed in SMEM
// (not registers) -> regs ~40, 6 CTAs/SM resident (vs 4) for latency hiding.
// No max pass: M_i = lrelu(s_i + max_j d_j) upper-bounds all row values
// (lrelu monotone), masked entries exp to exactly 0. One reduce only.
__global__ __launch_bounds__(256, 6) void softmax_kernel(const float* __restrict__ adj,
                                                         float* __restrict__ out) {
    __shared__ float row[N_NODES];   // 32 KB exp stash
    __shared__ float red[8];
    const int i = blockIdx.x;
    const int t = threadIdx.x;
    const float si = g_s[i];

    // Fold 64 per-block d-maxes (L1-hot) with 4 independent chains.
    float D0 = -INFINITY, D1 = -INFINITY, D2 = -INFINITY, D3 = -INFINITY;
    #pragma unroll
    for (int b = 0; b < SD_BLOCKS; b += 4) {
        D0 = fmaxf(D0, __ldg(&g_bmax[b + 0]));
        D1 = fmaxf(D1, __ldg(&g_bmax[b + 1]));
        D2 = fmaxf(D2, __ldg(&g_bmax[b + 2]));
        D3 = fmaxf(D3, __ldg(&g_bmax[b + 3]));
    }
    float M = si + fmaxf(fmaxf(D0, D1), fmaxf(D2, D3));
    M = M >= 0.f ? M : NEG_SLOPE * M;

    const float4* ap = reinterpret_cast<const float4*>(adj + (size_t)i * N_NODES);
    const float4* dp = reinterpret_cast<const float4*>(g_d);
    float4* rp = reinterpret_cast<float4*>(row);

    // Pass 1: load adj (streaming) + d (cached), exp, stash to smem, sum.
    float lsum = 0.f;
    #pragma unroll
    for (int k = 0; k < 8; ++k) {
        const int c = t + k * 256;
        float4 av = __ldcs(&ap[c]);
        float4 dv = __ldg(&dp[c]);
        float v0 = si + dv.x; v0 = v0 >= 0.f ? v0 : NEG_SLOPE * v0; v0 = (av.x > 0.f) ? v0 : -VERY_SMALL;
        float v1 = si + dv.y; v1 = v1 >= 0.f ? v1 : NEG_SLOPE * v1; v1 = (av.y > 0.f) ? v1 : -VERY_SMALL;
        float v2 = si + dv.z; v2 = v2 >= 0.f ? v2 : NEG_SLOPE * v2; v2 = (av.z > 0.f) ? v2 : -VERY_SMALL;
        float v3 = si + dv.w; v3 = v3 >= 0.f ? v3 : NEG_SLOPE * v3; v3 = (av.w > 0.f) ? v3 : -VERY_SMALL;
        float4 e;
        e.x = __expf(v0 - M);
        e.y = __expf(v1 - M);
        e.z = __expf(v2 - M);
        e.w = __expf(v3 - M);
        rp[c] = e;
        lsum += (e.x + e.y) + (e.z + e.w);
    }
    const float ssum = block_reduce_sum(lsum, red);
    const float inv = 1.0f / ssum;

    // Pass 2: read stash, normalize, streaming store.
    float4* op = reinterpret_cast<float4*>(out + (size_t)i * N_NODES);
    #pragma unroll
    for (int k = 0; k < 8; ++k) {
        const int c = t + k * 256;
        float4 o = rp[c];
        o.x *= inv; o.y *= inv; o.z *= inv; o.w *= inv;
        __stcs(&op[c], o);
    }
}

extern "C" void kernel_launch(void* const* d_in, const int* in_sizes, int n_in,
                              void* d_out, int out_size) {
    const float* h   = (const float*)d_in[0];  // [8192,128]
    const float* adj = (const float*)d_in[1];  // [8192,8192]
    const float* w   = (const float*)d_in[2];  // [128,64]
    const float* a   = (const float*)d_in[3];  // [128,1]
    float* out = (float*)d_out;

    sd_kernel<<<SD_BLOCKS, 256>>>(h, w, a);
    softmax_kernel<<<N_NODES, 256>>>(adj, out);
}

// round 6
// speedup vs baseline: 1.1075x; 1.1075x over previous
#include <cuda_runtime.h>
#include <math.h>

#define N_NODES 8192
#define F_IN 128
#define F_OUT 64
#define NEG_SLOPE 0.2f
#define VERY_SMALL 1000000000000.0f
#define SD_BLOCKS 256
#define ROWS_PER_SD_BLOCK (N_NODES / SD_BLOCKS)   // 32

__device__ float g_s[N_NODES];
__device__ float g_d[N_NODES];
__device__ float g_bmax[SD_BLOCKS];   // per-block max of d

// Kernel A: fused prep + sd + per-block d-max. 256 blocks x 256 thr, 32 rows.
__global__ __launch_bounds__(256) void sd_kernel(const float* __restrict__ h,
                                                 const float* __restrict__ w,
                                                 const float* __restrict__ a) {
    __shared__ float sw[F_IN * 65];   // padded: conflict-free row reads
    __shared__ float sa[F_IN];
    __shared__ float ws[F_IN];
    __shared__ float wd[F_IN];
    __shared__ float wmax[8];
    const int t = threadIdx.x;

    if (t < F_IN) sa[t] = a[t];
    const float4* w4 = reinterpret_cast<const float4*>(w);
    #pragma unroll
    for (int r = 0; r < 8; ++r) {
        int f = t + r * 256;
        float4 v = w4[f];
        int k = f >> 4;
        int j = (f & 15) * 4;
        float* dst = &sw[k * 65 + j];
        dst[0] = v.x; dst[1] = v.y; dst[2] = v.z; dst[3] = v.w;
    }
    __syncthreads();

    {   // threads 0-127: ws[k]; 128-255: wd[k]
        int k = t & 127;
        const float* arow = sa + ((t >= 128) ? F_OUT : 0);
        const float* wrow = &sw[k * 65];
        float acc = 0.f;
        #pragma unroll
        for (int j = 0; j < F_OUT; ++j)
            acc += wrow[j] * arow[j];
        if (t < 128) ws[k] = acc; else wd[k] = acc;
    }
    __syncthreads();

    const int warp = t >> 5;
    const int lane = t & 31;
    const int base = blockIdx.x * ROWS_PER_SD_BLOCK + warp * (ROWS_PER_SD_BLOCK / 8);
    const float4 wsv = reinterpret_cast<const float4*>(ws)[lane];
    const float4 wdv = reinterpret_cast<const float4*>(wd)[lane];

    float dmax = -INFINITY;
    #pragma unroll
    for (int rr = 0; rr < ROWS_PER_SD_BLOCK / 8; ++rr) {
        const int i = base + rr;
        float4 hv = reinterpret_cast<const float4*>(h + (size_t)i * F_IN)[lane];
        float s = hv.x * wsv.x + hv.y * wsv.y + hv.z * wsv.z + hv.w * wsv.w;
        float d = hv.x * wdv.x + hv.y * wdv.y + hv.z * wdv.z + hv.w * wdv.w;
        #pragma unroll
        for (int o = 16; o > 0; o >>= 1) {
            s += __shfl_xor_sync(0xffffffffu, s, o);
            d += __shfl_xor_sync(0xffffffffu, d, o);
        }
        if (lane == 0) { g_s[i] = s; g_d[i] = d; dmax = fmaxf(dmax, d); }
    }
    if (lane == 0) wmax[warp] = dmax;
    __syncthreads();
    if (t == 0) {
        float m = wmax[0];
        #pragma unroll
        for (int k = 1; k < 8; ++k) m = fmaxf(m, wmax[k]);
        g_bmax[blockIdx.x] = m;
    }
}

__device__ __forceinline__ float block_reduce_sum(float v, float* red) {
    #pragma unroll
    for (int o = 16; o > 0; o >>= 1)
        v += __shfl_xor_sync(0xffffffffu, v, o);
    int warp = threadIdx.x >> 5;
    if ((threadIdx.x & 31) == 0) red[warp] = v;
    __syncthreads();
    if (warp == 0) {
        float x = (threadIdx.x < 8) ? red[threadIdx.x] : 0.f;
        #pragma unroll
        for (int o = 4; o > 0; o >>= 1)
            x += __shfl_xor_sync(0xffffffffu, x, o);
        if (threadIdx.x == 0) red[0] = x;
    }
    __syncthreads();
    return red[0];
}

// Kernel B: one CTA (256 threads) per row.
//  - all 8 adj float4 front-batched into e[8] (max MLP), then overwritten
//    in place with exp values (stash == load buffer, 32 regs)
//  - stabilizer M = lrelu(s_i + max_j d_j): warp-parallel fold of 256
//    per-block maxes (~10 instrs), no max reduce over the row
//  - ONE block reduce (sum), streaming loads/stores
__global__ __launch_bounds__(256, 5) void softmax_kernel(const float* __restrict__ adj,
                                                         float* __restrict__ out) {
    __shared__ float red[8];
    const int i = blockIdx.x;
    const int t = threadIdx.x;
    const int lane = t & 31;
    const float si = g_s[i];

    // Warp-parallel D fold: 256 bmax values = 64 float4; lanes cover 2 each.
    const float4* bm4 = reinterpret_cast<const float4*>(g_bmax);
    float4 m0 = __ldg(&bm4[lane]);
    float4 m1 = __ldg(&bm4[lane + 32]);
    float D = fmaxf(fmaxf(fmaxf(m0.x, m0.y), fmaxf(m0.z, m0.w)),
                    fmaxf(fmaxf(m1.x, m1.y), fmaxf(m1.z, m1.w)));
    #pragma unroll
    for (int o = 16; o > 0; o >>= 1)
        D = fmaxf(D, __shfl_xor_sync(0xffffffffu, D, o));
    float M = si + D;
    M = M >= 0.f ? M : NEG_SLOPE * M;

    const float4* ap = reinterpret_cast<const float4*>(adj + (size_t)i * N_NODES);
    const float4* dp = reinterpret_cast<const float4*>(g_d);

    // Front-batch all adj loads (single base reg + immediate offsets).
    float4 e[8];
    #pragma unroll
    for (int k = 0; k < 8; ++k)
        e[k] = __ldcs(&ap[t + k * 256]);

    float lsum = 0.f;
    #pragma unroll
    for (int k = 0; k < 8; ++k) {
        float4 dv = __ldg(&dp[t + k * 256]);   // L1-resident (32 KB, all CTAs)
        float4 av = e[k];
        float v0 = si + dv.x; v0 = v0 >= 0.f ? v0 : NEG_SLOPE * v0;
        float v1 = si + dv.y; v1 = v1 >= 0.f ? v1 : NEG_SLOPE * v1;
        float v2 = si + dv.z; v2 = v2 >= 0.f ? v2 : NEG_SLOPE * v2;
        float v3 = si + dv.w; v3 = v3 >= 0.f ? v3 : NEG_SLOPE * v3;
        e[k].x = (av.x > 0.f) ? __expf(v0 - M) : 0.f;
        e[k].y = (av.y > 0.f) ? __expf(v1 - M) : 0.f;
        e[k].z = (av.z > 0.f) ? __expf(v2 - M) : 0.f;
        e[k].w = (av.w > 0.f) ? __expf(v3 - M) : 0.f;
        lsum += (e[k].x + e[k].y) + (e[k].z + e[k].w);
    }
    const float ssum = block_reduce_sum(lsum, red);
    const float inv = 1.0f / ssum;

    float4* op = reinterpret_cast<float4*>(out + (size_t)i * N_NODES);
    #pragma unroll
    for (int k = 0; k < 8; ++k) {
        float4 o = e[k];
        o.x *= inv; o.y *= inv; o.z *= inv; o.w *= inv;
        __stcs(&op[t + k * 256], o);
    }
}

extern "C" void kernel_launch(void* const* d_in, const int* in_sizes, int n_in,
                              void* d_out, int out_size) {
    const float* h   = (const float*)d_in[0];  // [8192,128]
    const float* adj = (const float*)d_in[1];  // [8192,8192]
    const float* w   = (const float*)d_in[2];  // [128,64]
    const float* a   = (const float*)d_in[3];  // [128,1]
    float* out = (float*)d_out;

    sd_kernel<<<SD_BLOCKS, 256>>>(h, w, a);
    softmax_kernel<<<N_NODES, 256>>>(adj, out);
}

// round 7
// speedup vs baseline: 1.3591x; 1.2271x over previous
#include <cuda_runtime.h>
#include <math.h>

#define N_NODES 8192
#define F_IN 128
#define F_OUT 64
#define NEG_SLOPE 0.2f
#define VERY_SMALL 1000000000000.0f
#define SD_BLOCKS 256
#define ROWS_PER_SD_BLOCK (N_NODES / SD_BLOCKS)   // 32

__device__ float g_s[N_NODES];
__device__ float g_d[N_NODES];
__device__ float g_bmax[SD_BLOCKS];   // per-block max of d

// Kernel A: fused prep + sd + per-block d-max. 256 blocks x 256 thr, 32 rows.
__global__ __launch_bounds__(256) void sd_kernel(const float* __restrict__ h,
                                                 const float* __restrict__ w,
                                                 const float* __restrict__ a) {
    __shared__ float sw[F_IN * 65];   // padded: conflict-free row reads
    __shared__ float sa[F_IN];
    __shared__ float ws[F_IN];
    __shared__ float wd[F_IN];
    __shared__ float wmax[8];
    const int t = threadIdx.x;

    if (t < F_IN) sa[t] = a[t];
    const float4* w4 = reinterpret_cast<const float4*>(w);
    #pragma unroll
    for (int r = 0; r < 8; ++r) {
        int f = t + r * 256;
        float4 v = w4[f];
        int k = f >> 4;
        int j = (f & 15) * 4;
        float* dst = &sw[k * 65 + j];
        dst[0] = v.x; dst[1] = v.y; dst[2] = v.z; dst[3] = v.w;
    }
    __syncthreads();

    {   // threads 0-127: ws[k]; 128-255: wd[k]
        int k = t & 127;
        const float* arow = sa + ((t >= 128) ? F_OUT : 0);
        const float* wrow = &sw[k * 65];
        float acc = 0.f;
        #pragma unroll
        for (int j = 0; j < F_OUT; ++j)
            acc += wrow[j] * arow[j];
        if (t < 128) ws[k] = acc; else wd[k] = acc;
    }
    __syncthreads();

    const int warp = t >> 5;
    const int lane = t & 31;
    const int base = blockIdx.x * ROWS_PER_SD_BLOCK + warp * (ROWS_PER_SD_BLOCK / 8);
    const float4 wsv = reinterpret_cast<const float4*>(ws)[lane];
    const float4 wdv = reinterpret_cast<const float4*>(wd)[lane];

    float dmax = -INFINITY;
    #pragma unroll
    for (int rr = 0; rr < ROWS_PER_SD_BLOCK / 8; ++rr) {
        const int i = base + rr;
        float4 hv = reinterpret_cast<const float4*>(h + (size_t)i * F_IN)[lane];
        float s = hv.x * wsv.x + hv.y * wsv.y + hv.z * wsv.z + hv.w * wsv.w;
        float d = hv.x * wdv.x + hv.y * wdv.y + hv.z * wdv.z + hv.w * wdv.w;
        #pragma unroll
        for (int o = 16; o > 0; o >>= 1) {
            s += __shfl_xor_sync(0xffffffffu, s, o);
            d += __shfl_xor_sync(0xffffffffu, d, o);
        }
        if (lane == 0) { g_s[i] = s; g_d[i] = d; dmax = fmaxf(dmax, d); }
    }
    if (lane == 0) wmax[warp] = dmax;
    __syncthreads();
    if (t == 0) {
        float m = wmax[0];
        #pragma unroll
        for (int k = 1; k < 8; ++k) m = fmaxf(m, wmax[k]);
        g_bmax[blockIdx.x] = m;
    }
}

__device__ __forceinline__ float block_reduce_sum(float v, float* red) {
    #pragma unroll
    for (int o = 16; o > 0; o >>= 1)
        v += __shfl_xor_sync(0xffffffffu, v, o);
    int warp = threadIdx.x >> 5;
    if ((threadIdx.x & 31) == 0) red[warp] = v;
    __syncthreads();
    if (warp == 0) {
        float x = (threadIdx.x < 8) ? red[threadIdx.x] : 0.f;
        #pragma unroll
        for (int o = 4; o > 0; o >>= 1)
            x += __shfl_xor_sync(0xffffffffu, x, o);
        if (threadIdx.x == 0) red[0] = x;
    }
    __syncthreads();
    return red[0];
}

// Kernel B: one CTA (256 threads) per row — R2 structure (interleaved loads,
// register stash, NO reg cap) with the max-reduce removed:
//   M = lrelu(s_i + max_j d_j) upper-bounds every row value (lrelu monotone),
//   masked entries go through v=-1e12 -> exp underflows to exactly 0.
// One fused load+lrelu+exp+sum pass, ONE block reduce, then store.
__global__ __launch_bounds__(256) void softmax_kernel(const float* __restrict__ adj,
                                                      float* __restrict__ out) {
    __shared__ float red[8];
    const int i = blockIdx.x;
    const int t = threadIdx.x;
    const int lane = t & 31;
    const float si = g_s[i];

    // Warp-parallel D fold: 256 bmax = 64 float4, 2 per lane, then 5 shfls.
    const float4* bm4 = reinterpret_cast<const float4*>(g_bmax);
    float4 m0 = __ldg(&bm4[lane]);
    float4 m1 = __ldg(&bm4[lane + 32]);
    float D = fmaxf(fmaxf(fmaxf(m0.x, m0.y), fmaxf(m0.z, m0.w)),
                    fmaxf(fmaxf(m1.x, m1.y), fmaxf(m1.z, m1.w)));
    #pragma unroll
    for (int o = 16; o > 0; o >>= 1)
        D = fmaxf(D, __shfl_xor_sync(0xffffffffu, D, o));
    float M = si + D;
    M = M >= 0.f ? M : NEG_SLOPE * M;

    const float4* ap = reinterpret_cast<const float4*>(adj + (size_t)i * N_NODES);
    const float4* dp = reinterpret_cast<const float4*>(g_d);

    float4 e[8];
    float lsum = 0.f;
    #pragma unroll
    for (int k = 0; k < 8; ++k) {
        const int c = t + k * 256;
        float4 av = __ldcs(&ap[c]);   // adj read once: evict-first
        float4 dv = __ldg(&dp[c]);    // 32 KB, reused by all CTAs: cached
        float v0 = si + dv.x; v0 = v0 >= 0.f ? v0 : NEG_SLOPE * v0; v0 = (av.x > 0.f) ? v0 : -VERY_SMALL;
        float v1 = si + dv.y; v1 = v1 >= 0.f ? v1 : NEG_SLOPE * v1; v1 = (av.y > 0.f) ? v1 : -VERY_SMALL;
        float v2 = si + dv.z; v2 = v2 >= 0.f ? v2 : NEG_SLOPE * v2; v2 = (av.z > 0.f) ? v2 : -VERY_SMALL;
        float v3 = si + dv.w; v3 = v3 >= 0.f ? v3 : NEG_SLOPE * v3; v3 = (av.w > 0.f) ? v3 : -VERY_SMALL;
        e[k].x = __expf(v0 - M);
        e[k].y = __expf(v1 - M);
        e[k].z = __expf(v2 - M);
        e[k].w = __expf(v3 - M);
        lsum += (e[k].x + e[k].y) + (e[k].z + e[k].w);
    }
    const float ssum = block_reduce_sum(lsum, red);
    const float inv = 1.0f / ssum;

    float4* op = reinterpret_cast<float4*>(out + (size_t)i * N_NODES);
    #pragma unroll
    for (int k = 0; k < 8; ++k) {
        const int c = t + k * 256;
        float4 o = e[k];
        o.x *= inv; o.y *= inv; o.z *= inv; o.w *= inv;
        __stcs(&op[c], o);   // out never re-read: streaming store
    }
}

extern "C" void kernel_launch(void* const* d_in, const int* in_sizes, int n_in,
                              void* d_out, int out_size) {
    const float* h   = (const float*)d_in[0];  // [8192,128]
    const float* adj = (const float*)d_in[1];  // [8192,8192]
    const float* w   = (const float*)d_in[2];  // [128,64]
    const float* a   = (const float*)d_in[3];  // [128,1]
    float* out = (float*)d_out;

    sd_kernel<<<SD_BLOCKS, 256>>>(h, w, a);
    softmax_kernel<<<N_NODES, 256>>>(adj, out);
}